// round 8
// baseline (speedup 1.0000x reference)
#include <cuda_runtime.h>
#include <math.h>

#define SIZE   1024
#define INPUT  1024
#define CTX    512
#define CMS    6
#define NSLOT  64
#define BATCH  128
#define SPER   8      // neurons per group in ctx kernels
#define KSPLIT 8
#define KPART  (CTX / KSPLIT)   // 64
#define KBLK   32

// Scratch (device globals — no allocation allowed)
__device__ float g_logT[BATCH * INPUT];            // logits^T: [b][i]
__device__ int   g_ctx [SIZE * BATCH];             // context index: [s][b]
__device__ float g_part[KSPLIT * SIZE * CMS * BATCH];  // 25MB partials

__device__ __forceinline__ void fma2(unsigned long long& d,
                                     unsigned long long a,
                                     unsigned long long b) {
    asm("fma.rn.f32x2 %0, %1, %2, %3;" : "=l"(d) : "l"(a), "l"(b), "l"(d));
}

// ---------------------------------------------------------------------------
// Kernel 1: ctx-hash partial GEMM. grid = 128 groups x 8 k-parts.
// Warp sl = neuron g*8+sl over c in [kp*64, kp*64+64). Lane = b-quad.
// Accum acc[m][q] packs two consecutive b per f32x2 -> x loads pre-packed
// (LDS.128 = 2 u64), proj pre-duplicated in smem (broadcast LDS.128):
// inner loop = 4 LDS + 12 FMA2, zero packing movs.
// ---------------------------------------------------------------------------
__global__ __launch_bounds__(256, 4) void ctx_part_k(
        const float* __restrict__ proj,
        const float* __restrict__ ctxin) {
    __shared__ float  s_x[KBLK][BATCH];          // 16KB
    __shared__ float4 s_p2[SPER][KBLK][3];       // 12KB [sl][c][jp]=(m0,m0,m1,m1)
    const int gid  = blockIdx.x;
    const int g    = gid >> 3;
    const int kp   = gid & 7;
    const int tid  = threadIdx.x;
    const int sl   = tid >> 5;
    const int lane = tid & 31;
    const int s0   = g * SPER;

    unsigned long long acc[CMS][2];   // [m][b-pair]
    #pragma unroll
    for (int m = 0; m < CMS; m++) { acc[m][0] = 0ull; acc[m][1] = 0ull; }

    for (int kb = 0; kb < KPART; kb += KBLK) {
        const int cbase = kp * KPART + kb;
        #pragma unroll
        for (int l = tid; l < KBLK * BATCH; l += 256)
            s_x[l >> 7][l & 127] =
                ctxin[(size_t)(cbase + (l >> 7)) * BATCH + (l & 127)];
        // proj tile, pre-duplicated: value (sl, m, c) -> s_p2[sl][c][m>>1] lanes {2(m&1), 2(m&1)+1}
        #pragma unroll
        for (int l = tid; l < SPER * CMS * KBLK; l += 256) {
            const int row = l >> 5;           // sl*CMS + m
            const int c   = l & 31;
            const int msl = row / CMS, m = row % CMS;
            const float v =
                proj[((size_t)(s0 + msl) * CMS + m) * CTX + cbase + c];
            float* dst = (float*)&s_p2[msl][c][m >> 1];
            dst[2 * (m & 1)]     = v;
            dst[2 * (m & 1) + 1] = v;
        }
        __syncthreads();

        #pragma unroll 8
        for (int c = 0; c < KBLK; c++) {
            const float4 xv = *(const float4*)&s_x[c][lane * 4];
            const unsigned long long xq0 = *(const unsigned long long*)&xv.x;
            const unsigned long long xq1 = *(const unsigned long long*)&xv.z;
            #pragma unroll
            for (int jp = 0; jp < 3; jp++) {
                const float4 pv = s_p2[sl][c][jp];
                const unsigned long long pd0 = *(const unsigned long long*)&pv.x;
                const unsigned long long pd1 = *(const unsigned long long*)&pv.z;
                fma2(acc[2 * jp][0],     pd0, xq0);
                fma2(acc[2 * jp][1],     pd0, xq1);
                fma2(acc[2 * jp + 1][0], pd1, xq0);
                fma2(acc[2 * jp + 1][1], pd1, xq1);
            }
        }
        __syncthreads();
    }

    // write partials: acc[m] = 4 consecutive b -> one float4, coalesced
    const size_t base = ((size_t)kp * SIZE + (s0 + sl)) * CMS * BATCH;
    #pragma unroll
    for (int m = 0; m < CMS; m++) {
        float4 v;
        *(unsigned long long*)&v.x = acc[m][0];
        *(unsigned long long*)&v.z = acc[m][1];
        *(float4*)&g_part[base + (size_t)m * BATCH + lane * 4] = v;
    }
}

// ---------------------------------------------------------------------------
// Kernel 2: reduce partials -> threshold -> g_ctx; folds logits transpose.
// grid 256, 512 threads: thread = (sl in [0,4), b); s = bx*4 + sl.
// ---------------------------------------------------------------------------
__global__ __launch_bounds__(512) void idx_k(
        const float* __restrict__ pbias,
        const float* __restrict__ logits) {
    __shared__ float s_t[4][BATCH];
    const int tid = threadIdx.x;
    const int sl  = tid >> 7;
    const int b   = tid & 127;
    const int s   = blockIdx.x * 4 + sl;
    const int i0  = blockIdx.x * 4;

    s_t[sl][b] = logits[(size_t)(i0 + sl) * BATCH + b];

    int idx = 0;
    const size_t sbase = (size_t)s * CMS * BATCH + b;
    #pragma unroll
    for (int m = 0; m < CMS; m++) {
        float sum = 0.0f;
        #pragma unroll
        for (int kpp = 0; kpp < KSPLIT; kpp++)
            sum += g_part[(size_t)kpp * SIZE * CMS * BATCH
                          + sbase + (size_t)m * BATCH];
        if (sum > __ldg(&pbias[(size_t)s * CMS + m])) idx |= (1 << m);
    }
    g_ctx[(size_t)s * BATCH + b] = idx;

    __syncthreads();
    g_logT[(size_t)b * INPUT + i0 + sl] = s_t[sl][b];
}

// ---------------------------------------------------------------------------
// Kernel 3: warp-per-row fused gather-dot / out / update / scatter-copy.
// ---------------------------------------------------------------------------
__global__ __launch_bounds__(256, 4) void main_k(
        const float* __restrict__ weights,
        const float* __restrict__ targets,
        const float* __restrict__ biasp,
        float* __restrict__ out,
        float* __restrict__ neww) {
    const int s    = blockIdx.y;
    const int tid  = threadIdx.x;
    const int lane = tid & 31;
    const int wid  = tid >> 5;
    const int slot = blockIdx.x * 8 + wid;

    __shared__ int s_ctx[BATCH];
    if (tid < BATCH) s_ctx[tid] = g_ctx[(size_t)s * BATCH + tid];

    const size_t rowoff = ((size_t)s * NSLOT + slot) * INPUT;
    const float4* wrow = (const float4*)(weights + rowoff);
    float4 w[8];
    #pragma unroll
    for (int k = 0; k < 8; k++) w[k] = __ldcs(wrow + k * 32 + lane);

    __syncthreads();

    int   last    = -1;
    float lasttot = 0.0f;

    #pragma unroll
    for (int j = 0; j < 4; j++) {
        const int bb0 = j * 32;
        const int v = s_ctx[bb0 + lane];
        unsigned m = __ballot_sync(0xffffffffu, v == slot);
        while (m) {
            const int bit = __ffs(m) - 1;
            m &= m - 1;
            const int bb = bb0 + bit;
            const float4* xr = (const float4*)(g_logT + (size_t)bb * INPUT);
            float acc = 0.0f;
            #pragma unroll
            for (int k = 0; k < 8; k++) {
                float4 x = __ldg(xr + k * 32 + lane);
                acc += w[k].x * x.x + w[k].y * x.y + w[k].z * x.z + w[k].w * x.w;
            }
            #pragma unroll
            for (int o = 16; o > 0; o >>= 1)
                acc += __shfl_xor_sync(0xffffffffu, acc, o);
            if (lane == 0)
                out[(size_t)s * BATCH + bb] = (s == 0) ? *biasp : acc;
            last = bb;            // ascending scan -> last-b-wins
            lasttot = acc;
        }
    }

    if (last >= 0) {
        float o  = (s == 0) ? *biasp : lasttot;
        float sg = 1.0f / (1.0f + expf(-o));
        sg = fminf(fmaxf(sg, 0.01f), 0.99f);
        const float g = 0.01f * (sg - __ldg(&targets[last]));
        const float4* xr = (const float4*)(g_logT + (size_t)last * INPUT);
        #pragma unroll
        for (int k = 0; k < 8; k++) {
            float4 x = __ldg(xr + k * 32 + lane);
            w[k].x = fminf(fmaxf(w[k].x - g * x.x, -5.0f), 5.0f);
            w[k].y = fminf(fmaxf(w[k].y - g * x.y, -5.0f), 5.0f);
            w[k].z = fminf(fmaxf(w[k].z - g * x.z, -5.0f), 5.0f);
            w[k].w = fminf(fmaxf(w[k].w - g * x.w, -5.0f), 5.0f);
        }
    }

    float4* orow = (float4*)(neww + rowoff);
    #pragma unroll
    for (int k = 0; k < 8; k++) __stcs(orow + k * 32 + lane, w[k]);
}

// ---------------------------------------------------------------------------
extern "C" void kernel_launch(void* const* d_in, const int* in_sizes, int n_in,
                              void* d_out, int out_size) {
    const float* logits  = (const float*)d_in[0];  // (1024, 128)
    const float* ctxin   = (const float*)d_in[1];  // (512, 128)
    const float* targets = (const float*)d_in[2];  // (128,)
    const float* proj    = (const float*)d_in[3];  // (1024, 6, 512)
    const float* pbias   = (const float*)d_in[4];  // (1024, 6, 1)
    const float* weights = (const float*)d_in[5];  // (1024, 64, 1024)
    const float* biasp   = (const float*)d_in[6];  // ()

    float* out  = (float*)d_out;                   // (1024, 128)
    float* neww = out + (size_t)SIZE * BATCH;      // (1024, 64, 1024)

    ctx_part_k<<<(SIZE / SPER) * KSPLIT, 256>>>(proj, ctxin);
    idx_k<<<SIZE / 4, 512>>>(pbias, logits);
    main_k<<<dim3(NSLOT / 8, SIZE), 256>>>(weights, targets, biasp, out, neww);
}

// round 9
// speedup vs baseline: 1.1111x; 1.1111x over previous
#include <cuda_runtime.h>
#include <math.h>

#define SIZE   1024
#define INPUT  1024
#define CTX    512
#define CMS    6
#define NSLOT  64
#define BATCH  128
#define SPER   8      // neurons per group in ctx kernels
#define KSPLIT 8
#define KPART  (CTX / KSPLIT)   // 64

// Scratch (device globals — no allocation allowed)
__device__ float g_logT[BATCH * INPUT];            // logits^T: [b][i]
__device__ int   g_ctx [SIZE * BATCH];             // context index: [s][b]
__device__ float g_part[KSPLIT * SIZE * CMS * BATCH];  // 25MB partials (L2-hot)

__device__ __forceinline__ void fma2(unsigned long long& d,
                                     unsigned long long a,
                                     unsigned long long b) {
    asm("fma.rn.f32x2 %0, %1, %2, %3;" : "=l"(d) : "l"(a), "l"(b), "l"(d));
}

// ---------------------------------------------------------------------------
// Kernel 1: ctx-hash partial GEMM. grid = 128 groups x 8 k-parts (1024 blocks).
// Whole KPART=64 slice staged in smem ONCE (single __syncthreads), then pure
// LDS+FMA2: per c, 1 x-LDS.128 (pre-packed b-pairs) + 3 broadcast proj-dup
// LDS.128 + 12 FMA2. No tile-boundary refill stalls.
// ---------------------------------------------------------------------------
__global__ __launch_bounds__(256, 4) void ctx_part_k(
        const float* __restrict__ proj,
        const float* __restrict__ ctxin) {
    __shared__ float  s_x[KPART][BATCH];          // 32KB
    __shared__ float4 s_p2[SPER][KPART][3];       // 24KB [sl][c][jp]=(m0,m0,m1,m1)
    const int gid  = blockIdx.x;
    const int g    = gid >> 3;
    const int kp   = gid & 7;
    const int tid  = threadIdx.x;
    const int sl   = tid >> 5;
    const int lane = tid & 31;
    const int s0   = g * SPER;
    const int cbase = kp * KPART;

    // ---- single load phase ----
    #pragma unroll
    for (int l = tid; l < KPART * BATCH; l += 256)
        s_x[l >> 7][l & 127] =
            ctxin[(size_t)(cbase + (l >> 7)) * BATCH + (l & 127)];
    #pragma unroll
    for (int l = tid; l < SPER * CMS * KPART; l += 256) {
        const int row = l >> 6;            // sl*CMS + m
        const int c   = l & 63;
        const int msl = row / CMS, m = row % CMS;
        const float v =
            proj[((size_t)(s0 + msl) * CMS + m) * CTX + cbase + c];
        float* dst = (float*)&s_p2[msl][c][m >> 1];
        dst[2 * (m & 1)]     = v;
        dst[2 * (m & 1) + 1] = v;
    }
    __syncthreads();

    // ---- pure compute: 64 c-iterations, no barriers ----
    unsigned long long acc[CMS][2];   // [m][b-pair]
    #pragma unroll
    for (int m = 0; m < CMS; m++) { acc[m][0] = 0ull; acc[m][1] = 0ull; }

    #pragma unroll 8
    for (int c = 0; c < KPART; c++) {
        const float4 xv = *(const float4*)&s_x[c][lane * 4];
        const unsigned long long xq0 = *(const unsigned long long*)&xv.x;
        const unsigned long long xq1 = *(const unsigned long long*)&xv.z;
        #pragma unroll
        for (int jp = 0; jp < 3; jp++) {
            const float4 pv = s_p2[sl][c][jp];
            const unsigned long long pd0 = *(const unsigned long long*)&pv.x;
            const unsigned long long pd1 = *(const unsigned long long*)&pv.z;
            fma2(acc[2 * jp][0],     pd0, xq0);
            fma2(acc[2 * jp][1],     pd0, xq1);
            fma2(acc[2 * jp + 1][0], pd1, xq0);
            fma2(acc[2 * jp + 1][1], pd1, xq1);
        }
    }

    // write partials: acc[m] = 4 consecutive b -> one float4, coalesced
    const size_t base = ((size_t)kp * SIZE + (s0 + sl)) * CMS * BATCH;
    #pragma unroll
    for (int m = 0; m < CMS; m++) {
        float4 v;
        *(unsigned long long*)&v.x = acc[m][0];
        *(unsigned long long*)&v.z = acc[m][1];
        *(float4*)&g_part[base + (size_t)m * BATCH + lane * 4] = v;
    }
}

// ---------------------------------------------------------------------------
// Kernel 2: reduce partials -> threshold -> g_ctx; folds logits transpose.
// grid 256, 512 threads: thread = (sl in [0,4), b); s = bx*4 + sl.
// ---------------------------------------------------------------------------
__global__ __launch_bounds__(512) void idx_k(
        const float* __restrict__ pbias,
        const float* __restrict__ logits) {
    __shared__ float s_t[4][BATCH];
    const int tid = threadIdx.x;
    const int sl  = tid >> 7;
    const int b   = tid & 127;
    const int s   = blockIdx.x * 4 + sl;
    const int i0  = blockIdx.x * 4;

    s_t[sl][b] = logits[(size_t)(i0 + sl) * BATCH + b];

    int idx = 0;
    const size_t sbase = (size_t)s * CMS * BATCH + b;
    #pragma unroll
    for (int m = 0; m < CMS; m++) {
        float sum = 0.0f;
        #pragma unroll
        for (int kpp = 0; kpp < KSPLIT; kpp++)
            sum += g_part[(size_t)kpp * SIZE * CMS * BATCH
                          + sbase + (size_t)m * BATCH];
        if (sum > __ldg(&pbias[(size_t)s * CMS + m])) idx |= (1 << m);
    }
    g_ctx[(size_t)s * BATCH + b] = idx;

    __syncthreads();
    g_logT[(size_t)b * INPUT + i0 + sl] = s_t[sl][b];
}

// ---------------------------------------------------------------------------
// Kernel 3: warp-per-row fused gather-dot / out / update / scatter-copy.
// ---------------------------------------------------------------------------
__global__ __launch_bounds__(256, 4) void main_k(
        const float* __restrict__ weights,
        const float* __restrict__ targets,
        const float* __restrict__ biasp,
        float* __restrict__ out,
        float* __restrict__ neww) {
    const int s    = blockIdx.y;
    const int tid  = threadIdx.x;
    const int lane = tid & 31;
    const int wid  = tid >> 5;
    const int slot = blockIdx.x * 8 + wid;

    __shared__ int s_ctx[BATCH];
    if (tid < BATCH) s_ctx[tid] = g_ctx[(size_t)s * BATCH + tid];

    const size_t rowoff = ((size_t)s * NSLOT + slot) * INPUT;
    const float4* wrow = (const float4*)(weights + rowoff);
    float4 w[8];
    #pragma unroll
    for (int k = 0; k < 8; k++) w[k] = __ldcs(wrow + k * 32 + lane);

    __syncthreads();

    int   last    = -1;
    float lasttot = 0.0f;

    #pragma unroll
    for (int j = 0; j < 4; j++) {
        const int bb0 = j * 32;
        const int v = s_ctx[bb0 + lane];
        unsigned m = __ballot_sync(0xffffffffu, v == slot);
        while (m) {
            const int bit = __ffs(m) - 1;
            m &= m - 1;
            const int bb = bb0 + bit;
            const float4* xr = (const float4*)(g_logT + (size_t)bb * INPUT);
            float acc = 0.0f;
            #pragma unroll
            for (int k = 0; k < 8; k++) {
                float4 x = __ldg(xr + k * 32 + lane);
                acc += w[k].x * x.x + w[k].y * x.y + w[k].z * x.z + w[k].w * x.w;
            }
            #pragma unroll
            for (int o = 16; o > 0; o >>= 1)
                acc += __shfl_xor_sync(0xffffffffu, acc, o);
            if (lane == 0)
                out[(size_t)s * BATCH + bb] = (s == 0) ? *biasp : acc;
            last = bb;            // ascending scan -> last-b-wins
            lasttot = acc;
        }
    }

    if (last >= 0) {
        float o  = (s == 0) ? *biasp : lasttot;
        float sg = 1.0f / (1.0f + expf(-o));
        sg = fminf(fmaxf(sg, 0.01f), 0.99f);
        const float g = 0.01f * (sg - __ldg(&targets[last]));
        const float4* xr = (const float4*)(g_logT + (size_t)last * INPUT);
        #pragma unroll
        for (int k = 0; k < 8; k++) {
            float4 x = __ldg(xr + k * 32 + lane);
            w[k].x = fminf(fmaxf(w[k].x - g * x.x, -5.0f), 5.0f);
            w[k].y = fminf(fmaxf(w[k].y - g * x.y, -5.0f), 5.0f);
            w[k].z = fminf(fmaxf(w[k].z - g * x.z, -5.0f), 5.0f);
            w[k].w = fminf(fmaxf(w[k].w - g * x.w, -5.0f), 5.0f);
        }
    }

    float4* orow = (float4*)(neww + rowoff);
    #pragma unroll
    for (int k = 0; k < 8; k++) __stcs(orow + k * 32 + lane, w[k]);
}

// ---------------------------------------------------------------------------
extern "C" void kernel_launch(void* const* d_in, const int* in_sizes, int n_in,
                              void* d_out, int out_size) {
    const float* logits  = (const float*)d_in[0];  // (1024, 128)
    const float* ctxin   = (const float*)d_in[1];  // (512, 128)
    const float* targets = (const float*)d_in[2];  // (128,)
    const float* proj    = (const float*)d_in[3];  // (1024, 6, 512)
    const float* pbias   = (const float*)d_in[4];  // (1024, 6, 1)
    const float* weights = (const float*)d_in[5];  // (1024, 64, 1024)
    const float* biasp   = (const float*)d_in[6];  // ()

    float* out  = (float*)d_out;                   // (1024, 128)
    float* neww = out + (size_t)SIZE * BATCH;      // (1024, 64, 1024)

    ctx_part_k<<<(SIZE / SPER) * KSPLIT, 256>>>(proj, ctxin);
    idx_k<<<SIZE / 4, 512>>>(pbias, logits);
    main_k<<<dim3(NSLOT / 8, SIZE), 256>>>(weights, targets, biasp, out, neww);
}